// round 14
// baseline (speedup 1.0000x reference)
#include <cuda_runtime.h>

// CenterLoss: loss = (1/B) * sum_i [ sxx/m^2 + scc - 2*sxc/m ],  m = max(sqrt(sxx),1e-12)
// B=16384, C=8192, D=64.
// R14 = R13 (best cold: 7.55us @ 806GB/s) with the reduction tail minimized:
//  - out zeroed by a cudaMemsetAsync graph node; each block does ONE
//    atomicAdd(out, partial) — no g_acc/g_count, no __threadfence, no
//    last-block finalize chain (removes 512 fences + 512 counter atomics +
//    the 3-deep dependent publish chain)
//  - everything else identical to R13: 512x256, R=2 rows/half-warp, float4
//    coalesced rows; shortest chain label LDG -> speculative center gather
//    (int32 view in-bounds for either dtype); probe+ballot dtype resolve
//    off-chain; rsqrt epilogue (MUFU.RSQ, validated)
// Model: kernel is at the idle-DVFS burst-bandwidth floor (~5.9MB compulsory
// at ~800GB/s); only tail cycles remained trimmable.

#define EPS 1e-12f
#define R 2   // rows per half-warp

__global__ void __launch_bounds__(256)
center_loss_kernel(const float4* __restrict__ x,
                   const void* __restrict__ labels,
                   const float4* __restrict__ centers,
                   float* __restrict__ out,
                   float inv_batch)
{
    __shared__ float ssum[8];

    const int tid  = threadIdx.x;
    const int lane = tid & 31;
    const int wid  = tid >> 5;
    const int hw   = lane >> 4;         // half-warp id
    const int sub  = lane & 15;         // lane within half-warp
    const int base = (((blockIdx.x * 8 + wid) * 2) + hw) * R;  // first of R rows

    // ---- chain head: labels first (int32 view, safe for either dtype:
    // int64 labels in [0,8192) reinterpret as alternating {label,0},
    // all valid centers rows) ----
    int2 lpair = ((const int2*)labels)[base >> 1];

    // probe (bytes 4..255, in-bounds for any dtype) — resolved later, off-chain
    unsigned int probe = ((const unsigned int*)labels)[2 * lane + 1];

    // independent x loads fill the label-load shadow
    float4 xv[R];
    #pragma unroll
    for (int i = 0; i < R; ++i)
        xv[i] = x[(base + i) * 16 + sub];

    // ---- speculative gather straight off lpair (no ballot in the chain) ----
    int lab[R];
    lab[0] = lpair.x; lab[1] = lpair.y;
    float4 cv[R];
    #pragma unroll
    for (int i = 0; i < R; ++i)
        cv[i] = centers[lab[i] * 16 + sub];

    // dtype resolution overlaps the gather; int64 labels => all probes zero
    bool is32 = __ballot_sync(0xffffffffu, probe != 0u) != 0u;
    if (!is32) {  // int64 correction path (never taken for this dataset)
        #pragma unroll
        for (int i = 0; i < R; ++i) {
            lab[i] = (int)((const long long*)labels)[base + i];
            cv[i]  = centers[lab[i] * 16 + sub];
        }
    }

    // ---- per-row sums + half-warp (16-lane) reduction ----
    float local = 0.0f;
    #pragma unroll
    for (int i = 0; i < R; ++i) {
        float sxx = xv[i].x*xv[i].x + xv[i].y*xv[i].y + xv[i].z*xv[i].z + xv[i].w*xv[i].w;
        float sxc = xv[i].x*cv[i].x + xv[i].y*cv[i].y + xv[i].z*cv[i].z + xv[i].w*cv[i].w;
        float scc = cv[i].x*cv[i].x + cv[i].y*cv[i].y + cv[i].z*cv[i].z + cv[i].w*cv[i].w;
        #pragma unroll
        for (int o = 8; o; o >>= 1) {
            sxx += __shfl_xor_sync(0xffffffffu, sxx, o);
            sxc += __shfl_xor_sync(0xffffffffu, sxc, o);
            scc += __shfl_xor_sync(0xffffffffu, scc, o);
        }
        if (sub == 0) {
            // r = 1/max(sqrt(sxx), EPS) via MUFU.RSQ; guard keeps r finite.
            float r = rsqrtf(fmaxf(sxx, 1e-24f));
            local += sxx * r * r + scc - 2.0f * sxc * r;
        }
    }
    // fold the two half-warps into lane 0 of each warp
    local += __shfl_xor_sync(0xffffffffu, local, 16);

    // ---- block reduce: 8 warp partials -> ONE atomic per block, done ----
    if (lane == 0) ssum[wid] = local;
    __syncthreads();
    if (tid == 0) {
        float s = 0.0f;
        #pragma unroll
        for (int i = 0; i < 8; ++i) s += ssum[i];
        atomicAdd(out, s * inv_batch);
    }
}

extern "C" void kernel_launch(void* const* d_in, const int* in_sizes, int n_in,
                              void* d_out, int out_size)
{
    const float4* x       = (const float4*)d_in[0];
    const void*   labels  = d_in[1];
    const float4* centers = (const float4*)d_in[2];
    float*        out     = (float*)d_out;

    const int batch = in_sizes[0] / 64;              // 16384

    // Zero the scalar output (capturable memset node), then accumulate into it.
    cudaMemsetAsync(out, 0, sizeof(float));

    const int rows_per_block = 8 * 2 * R;            // 32
    const int blocks = batch / rows_per_block;       // 512
    center_loss_kernel<<<blocks, 256>>>(x, labels, centers, out,
                                        1.0f / (float)batch);
}

// round 15
// speedup vs baseline: 1.0528x; 1.0528x over previous
#include <cuda_runtime.h>

// CenterLoss: loss = (1/B) * sum_i [ sxx/m^2 + scc - 2*sxc/m ],  m = max(sqrt(sxx),1e-12)
// B=16384, C=8192, D=64.
// R15 = R14's fast kernel body (cold 6.24us @ 976GB/s) + single-node launch.
// Session finding: each graph node costs ~1-1.3us in replay, so the memset
// node must go. In-kernel finalize returns, but cheap:
//  - NO __threadfence: the g_acc atomicAdd's RETURN VALUE is consumed to form
//    the counter increment (always 1, but data-dependent & unfoldable), so the
//    counter atomic issues only after the sum completed at L2.
//  - last block: atomicExch(g_acc,0) -> *out -> plain reset of g_count
//    (no other blocks active). Deterministic across graph replays.
// Body identical to R14: 512x256, R=2 rows/half-warp, float4 coalesced rows;
// chain = label LDG -> speculative center gather (int32 view in-bounds for
// either dtype); probe+ballot dtype resolve off-chain; rsqrt epilogue.

#define EPS 1e-12f
#define R 2   // rows per half-warp

__device__ float g_acc;            // zero at load; reset by finalizer each run
__device__ unsigned int g_count;   // ditto

__global__ void __launch_bounds__(256)
center_loss_kernel(const float4* __restrict__ x,
                   const void* __restrict__ labels,
                   const float4* __restrict__ centers,
                   float* __restrict__ out,
                   float inv_batch)
{
    __shared__ float ssum[8];

    const int tid  = threadIdx.x;
    const int lane = tid & 31;
    const int wid  = tid >> 5;
    const int hw   = lane >> 4;         // half-warp id
    const int sub  = lane & 15;         // lane within half-warp
    const int base = (((blockIdx.x * 8 + wid) * 2) + hw) * R;  // first of R rows

    // ---- chain head: labels first (int32 view, safe for either dtype:
    // int64 labels in [0,8192) reinterpret as alternating {label,0},
    // all valid centers rows) ----
    int2 lpair = ((const int2*)labels)[base >> 1];

    // probe (bytes 4..255, in-bounds for any dtype) — resolved later, off-chain
    unsigned int probe = ((const unsigned int*)labels)[2 * lane + 1];

    // independent x loads fill the label-load shadow
    float4 xv[R];
    #pragma unroll
    for (int i = 0; i < R; ++i)
        xv[i] = x[(base + i) * 16 + sub];

    // ---- speculative gather straight off lpair (no ballot in the chain) ----
    int lab[R];
    lab[0] = lpair.x; lab[1] = lpair.y;
    float4 cv[R];
    #pragma unroll
    for (int i = 0; i < R; ++i)
        cv[i] = centers[lab[i] * 16 + sub];

    // dtype resolution overlaps the gather; int64 labels => all probes zero
    bool is32 = __ballot_sync(0xffffffffu, probe != 0u) != 0u;
    if (!is32) {  // int64 correction path (never taken for this dataset)
        #pragma unroll
        for (int i = 0; i < R; ++i) {
            lab[i] = (int)((const long long*)labels)[base + i];
            cv[i]  = centers[lab[i] * 16 + sub];
        }
    }

    // ---- per-row sums + half-warp (16-lane) reduction ----
    float local = 0.0f;
    #pragma unroll
    for (int i = 0; i < R; ++i) {
        float sxx = xv[i].x*xv[i].x + xv[i].y*xv[i].y + xv[i].z*xv[i].z + xv[i].w*xv[i].w;
        float sxc = xv[i].x*cv[i].x + xv[i].y*cv[i].y + xv[i].z*cv[i].z + xv[i].w*cv[i].w;
        float scc = cv[i].x*cv[i].x + cv[i].y*cv[i].y + cv[i].z*cv[i].z + cv[i].w*cv[i].w;
        #pragma unroll
        for (int o = 8; o; o >>= 1) {
            sxx += __shfl_xor_sync(0xffffffffu, sxx, o);
            sxc += __shfl_xor_sync(0xffffffffu, sxc, o);
            scc += __shfl_xor_sync(0xffffffffu, scc, o);
        }
        if (sub == 0) {
            // r = 1/max(sqrt(sxx), EPS) via MUFU.RSQ; guard keeps r finite.
            float r = rsqrtf(fmaxf(sxx, 1e-24f));
            local += sxx * r * r + scc - 2.0f * sxc * r;
        }
    }
    // fold the two half-warps into lane 0 of each warp
    local += __shfl_xor_sync(0xffffffffu, local, 16);

    // ---- block reduce: 8 warp partials -> fenceless two-atomic finalize ----
    if (lane == 0) ssum[wid] = local;
    __syncthreads();
    if (tid == 0) {
        float s = 0.0f;
        #pragma unroll
        for (int i = 0; i < 8; ++i) s += ssum[i];

        // Returned value forces completion at L2 before we signal arrival.
        float prev = atomicAdd(&g_acc, s);
        // inc is always 1, but data-depends on prev -> cannot be reordered
        // ahead of the g_acc completion, and cannot be constant-folded.
        unsigned int inc = (__float_as_uint(prev) != 0xdeadbeefu) ? 1u : 2u;
        unsigned int old = atomicAdd(&g_count, inc);
        if (old == gridDim.x - 1u) {
            float total = atomicExch(&g_acc, 0.0f);  // read + reset, coherent
            *out = total * inv_batch;
            g_count = 0u;                            // no other blocks active
        }
    }
}

extern "C" void kernel_launch(void* const* d_in, const int* in_sizes, int n_in,
                              void* d_out, int out_size)
{
    const float4* x       = (const float4*)d_in[0];
    const void*   labels  = d_in[1];
    const float4* centers = (const float4*)d_in[2];
    float*        out     = (float*)d_out;

    const int batch = in_sizes[0] / 64;              // 16384
    const int rows_per_block = 8 * 2 * R;            // 32
    const int blocks = batch / rows_per_block;       // 512
    center_loss_kernel<<<blocks, 256>>>(x, labels, centers, out,
                                        1.0f / (float)batch);
}

// round 16
// speedup vs baseline: 1.2857x; 1.2212x over previous
#include <cuda_runtime.h>

// CenterLoss: loss = (1/B) * sum_i [ sxx/m^2 + scc - 2*sxc/m ],  m = max(sqrt(sxx),1e-12)
// B=16384, C=8192, D=64.
// R16 = R14's fast body (cold 6.24us @ 976GB/s) + SINGLE packed-atomic finalize.
// Finding chain: R14 proved the body runs 6.24us with a one-atomic tail, but its
// memset graph node cost ~1.2us in replay; R13/R15 proved a two-atomic finalize
// (fenced or fenceless) costs +1.3us of exposed tail. Fix: ONE 64-bit atomicAdd
// carries BOTH the sum (fixed-point, bits [0:54)) and the arrival count
// (bits [54:64)). Valid because every distmat term is a squared distance >= 0
// (partial<=~5e3, total<2^45 << 2^54). The atomic's return value identifies the
// last block AND provides the prior sum, so the last block finishes with plain
// stores: *out and a reset of the accumulator (no other writers alive;
// kernel-exit membar publishes the reset for the next graph replay).
// Fixed-point accumulation is exact & order-independent -> deterministic.
// Body: 512x256, R=2 rows/half-warp, float4 coalesced rows; chain = label LDG
// -> speculative center gather (int32 view in-bounds for either dtype);
// probe+ballot dtype resolve off-chain; rsqrt epilogue.

#define EPS 1e-12f
#define R 2   // rows per half-warp

#define CNT_ONE   (1ULL << 54)
#define SUM_MASK  (CNT_ONE - 1ULL)
#define FX_SCALE  4294967296.0   // 2^32

__device__ unsigned long long g_pack;   // zero at load; reset by last block each run

__global__ void __launch_bounds__(256)
center_loss_kernel(const float4* __restrict__ x,
                   const void* __restrict__ labels,
                   const float4* __restrict__ centers,
                   float* __restrict__ out,
                   float inv_batch)
{
    __shared__ float ssum[8];

    const int tid  = threadIdx.x;
    const int lane = tid & 31;
    const int wid  = tid >> 5;
    const int hw   = lane >> 4;         // half-warp id
    const int sub  = lane & 15;         // lane within half-warp
    const int base = (((blockIdx.x * 8 + wid) * 2) + hw) * R;  // first of R rows

    // ---- chain head: labels first (int32 view, safe for either dtype:
    // int64 labels in [0,8192) reinterpret as alternating {label,0},
    // all valid centers rows) ----
    int2 lpair = ((const int2*)labels)[base >> 1];

    // probe (bytes 4..255, in-bounds for any dtype) — resolved later, off-chain
    unsigned int probe = ((const unsigned int*)labels)[2 * lane + 1];

    // independent x loads fill the label-load shadow
    float4 xv[R];
    #pragma unroll
    for (int i = 0; i < R; ++i)
        xv[i] = x[(base + i) * 16 + sub];

    // ---- speculative gather straight off lpair (no ballot in the chain) ----
    int lab[R];
    lab[0] = lpair.x; lab[1] = lpair.y;
    float4 cv[R];
    #pragma unroll
    for (int i = 0; i < R; ++i)
        cv[i] = centers[lab[i] * 16 + sub];

    // dtype resolution overlaps the gather; int64 labels => all probes zero
    bool is32 = __ballot_sync(0xffffffffu, probe != 0u) != 0u;
    if (!is32) {  // int64 correction path (never taken for this dataset)
        #pragma unroll
        for (int i = 0; i < R; ++i) {
            lab[i] = (int)((const long long*)labels)[base + i];
            cv[i]  = centers[lab[i] * 16 + sub];
        }
    }

    // ---- per-row sums + half-warp (16-lane) reduction ----
    float local = 0.0f;
    #pragma unroll
    for (int i = 0; i < R; ++i) {
        float sxx = xv[i].x*xv[i].x + xv[i].y*xv[i].y + xv[i].z*xv[i].z + xv[i].w*xv[i].w;
        float sxc = xv[i].x*cv[i].x + xv[i].y*cv[i].y + xv[i].z*cv[i].z + xv[i].w*cv[i].w;
        float scc = cv[i].x*cv[i].x + cv[i].y*cv[i].y + cv[i].z*cv[i].z + cv[i].w*cv[i].w;
        #pragma unroll
        for (int o = 8; o; o >>= 1) {
            sxx += __shfl_xor_sync(0xffffffffu, sxx, o);
            sxc += __shfl_xor_sync(0xffffffffu, sxc, o);
            scc += __shfl_xor_sync(0xffffffffu, scc, o);
        }
        if (sub == 0) {
            // r = 1/max(sqrt(sxx), EPS) via MUFU.RSQ; guard keeps r finite.
            float r = rsqrtf(fmaxf(sxx, 1e-24f));
            local += sxx * r * r + scc - 2.0f * sxc * r;
        }
    }
    // fold the two half-warps into lane 0 of each warp
    local += __shfl_xor_sync(0xffffffffu, local, 16);

    // ---- block reduce: 8 warp partials -> ONE packed atomic ----
    if (lane == 0) ssum[wid] = local;
    __syncthreads();
    if (tid == 0) {
        float s = 0.0f;
        #pragma unroll
        for (int i = 0; i < 8; ++i) s += ssum[i];

        // partial >= 0 (sum of squared distances); pack as 2^32 fixed point.
        unsigned long long fx = (unsigned long long)((double)s * FX_SCALE);
        unsigned long long old = atomicAdd(&g_pack, CNT_ONE + fx);
        if ((old >> 54) == gridDim.x - 1u) {
            // Last arrival: prior sum is in the return value — no more atomics.
            unsigned long long total_fx = (old & SUM_MASK) + fx;
            *out = (float)((double)total_fx * (1.0 / FX_SCALE) * (double)inv_batch);
            g_pack = 0ULL;   // sole live writer; kernel-exit membar publishes
        }
    }
}

extern "C" void kernel_launch(void* const* d_in, const int* in_sizes, int n_in,
                              void* d_out, int out_size)
{
    const float4* x       = (const float4*)d_in[0];
    const void*   labels  = d_in[1];
    const float4* centers = (const float4*)d_in[2];
    float*        out     = (float*)d_out;

    const int batch = in_sizes[0] / 64;              // 16384
    const int rows_per_block = 8 * 2 * R;            // 32
    const int blocks = batch / rows_per_block;       // 512
    center_loss_kernel<<<blocks, 256>>>(x, labels, centers, out,
                                        1.0f / (float)batch);
}